// round 2
// baseline (speedup 1.0000x reference)
#include <cuda_runtime.h>
#include <math.h>

// CNO_LReLu: per-row (B*C = 8192 rows of 2048 fp32):
//   y   = bicubic_antialias_upsample_x2(x)      (2048 -> 4096)
//   y   = leaky_relu(y, 0.01)
//   out = bicubic_antialias_downsample_x2(y)    (4096 -> 2048)
//
// Register-blocked: each thread computes 4 contiguous outputs from 12 x values
// (3 aligned float4 loads). No shared memory, no syncthreads.
// Interior stencils are exact dyadic constants (sum to 1 exactly, matching the
// reference's renormalization). Edge slots t=0 and t=511 use the generic
// drop-OOB + renormalize path.

#define IN_N   2048
#define MID_N  4096
#define OUT_N  2048
#define N_ROWS 8192
#define SLOTS  512          // outputs-per-row / 4

__device__ __forceinline__ float keys_cubic(float x) {
    float ax = fabsf(x);
    if (ax <= 1.0f) return (1.5f * ax - 2.5f) * ax * ax + 1.0f;
    if (ax < 2.0f)  return -0.5f * (((ax - 5.0f) * ax + 8.0f) * ax - 4.0f);
    return 0.0f;
}

// Generic upsample output m (fscale=1, 5 taps), OOB drop + renorm, then leaky.
__device__ __forceinline__ float gen_up_leaky(const float* __restrict__ xr, int m) {
    float center = (m + 0.5f) * 0.5f;
    int xmin = (int)floorf(center - 1.5f);
    float sum = 0.0f, acc = 0.0f;
#pragma unroll
    for (int tp = 0; tp < 5; tp++) {
        int idx = xmin + tp;
        float w = keys_cubic((float)idx + 0.5f - center);
        if (idx >= 0 && idx < IN_N) {
            sum += w;
            acc = fmaf(w, xr[idx], acc);
        }
    }
    float v = acc / sum;
    return (v >= 0.0f) ? v : 0.01f * v;
}

// Generic downsample output o (fscale=2, 9 taps), OOB drop + renorm.
__device__ __forceinline__ float gen_down(const float* __restrict__ xr, int o) {
    float center = (o + 0.5f) * 2.0f;
    int xmin = (int)floorf(center - 3.5f);
    float sum = 0.0f, acc = 0.0f;
#pragma unroll
    for (int tp = 0; tp < 9; tp++) {
        int idx = xmin + tp;
        float w = keys_cubic(((float)idx + 0.5f - center) * 0.5f);
        if (idx >= 0 && idx < MID_N) {
            sum += w;
            acc = fmaf(w, gen_up_leaky(xr, idx), acc);
        }
    }
    return acc / sum;
}

// Symmetric interior downsample over 8 mid values y[0..7]:
// DW = {-3,-9,29,111,111,29,-9,-3}/256
__device__ __forceinline__ float dsum(const float* y) {
    return fmaf(0.43359375f,  (y[3] + y[4]),
           fmaf(0.11328125f,  (y[2] + y[5]),
           fmaf(-0.03515625f, (y[1] + y[6]),
                -0.01171875f * (y[0] + y[7]))));
}

__global__ __launch_bounds__(256) void cno_lrelu_kernel(
    const float* __restrict__ x, float* __restrict__ out)
{
    const int g   = blockIdx.x * 256 + threadIdx.x;
    const int row = g >> 9;          // g / SLOTS
    const int t   = g & (SLOTS - 1); // slot within row
    const float* __restrict__ xr = x + (size_t)row * IN_N;
    float4* __restrict__ ov = reinterpret_cast<float4*>(out) + (size_t)row * SLOTS + t;

    if (t >= 1 && t <= SLOTS - 2) {
        // ---- interior fast path ----
        const float4* __restrict__ xv = reinterpret_cast<const float4*>(xr) + t;
        float4 A = xv[-1], B = xv[0], C = xv[1];
        float xl[12] = { A.x, A.y, A.z, A.w,
                         B.x, B.y, B.z, B.w,
                         C.x, C.y, C.z, C.w };
        // xl[i] = x[4t - 4 + i]

        // 14 mid values y[8t-3 .. 8t+10], with LeakyReLU applied.
        // p odd  -> even mid index m=2k, k=4t+(p-3)/2:
        //   yE = {-6,58,222,-18}/256 over x[k-2..k+1]  (xl base i=(p-3)/2+2)
        // p even -> odd  mid index m=2k+1, k=4t+(p-4)/2:
        //   yO = {-18,222,58,-6}/256 over x[k-1..k+2]  (xl base i=(p-4)/2+3)
        float ym[14];
#pragma unroll
        for (int p = 0; p < 14; p++) {
            float v;
            if (p & 1) {
                int i = (p - 3) / 2 + 2;
                v = fmaf(-0.0234375f, xl[i],
                    fmaf( 0.2265625f, xl[i + 1],
                    fmaf( 0.8671875f, xl[i + 2], -0.0703125f * xl[i + 3])));
            } else {
                int i = (p - 4) / 2 + 3;
                v = fmaf(-0.0703125f, xl[i],
                    fmaf( 0.8671875f, xl[i + 1],
                    fmaf( 0.2265625f, xl[i + 2], -0.0234375f * xl[i + 3])));
            }
            ym[p] = (v >= 0.0f) ? v : 0.01f * v;
        }

        // 4 outputs; output o=4t+i uses ym[2i .. 2i+7]
        float4 r;
        r.x = dsum(ym + 0);
        r.y = dsum(ym + 2);
        r.z = dsum(ym + 4);
        r.w = dsum(ym + 6);
        *ov = r;
    } else {
        // ---- edge slots (t==0, t==SLOTS-1): generic path ----
        float4 r;
        int o0 = 4 * t;
        r.x = gen_down(xr, o0 + 0);
        r.y = gen_down(xr, o0 + 1);
        r.z = gen_down(xr, o0 + 2);
        r.w = gen_down(xr, o0 + 3);
        *ov = r;
    }
}

extern "C" void kernel_launch(void* const* d_in, const int* in_sizes, int n_in,
                              void* d_out, int out_size) {
    const float* x = (const float*)d_in[0];
    float* out = (float*)d_out;
    (void)in_sizes; (void)n_in; (void)out_size;
    // 8192 rows * 512 slots / 256 threads = 16384 blocks
    cno_lrelu_kernel<<<(N_ROWS * SLOTS) / 256, 256>>>(x, out);
}

// round 4
// speedup vs baseline: 6.2713x; 6.2713x over previous
#include <cuda_runtime.h>
#include <math.h>

// CNO_LReLu: per-row (8192 rows of 2048 fp32):
//   y = bicubic_antialias_upsample_x2(x); y = leaky_relu(y, 0.01);
//   out = bicubic_antialias_downsample_x2(y)
//
// Register-blocked: each thread computes 4 contiguous outputs from 3 aligned
// float4 loads. No shared memory. All stencils (interior AND edge) are
// hardcoded exact rationals matching the reference's drop-OOB + renormalize.

#define IN_N   2048
#define OUT_N  2048
#define N_ROWS 8192
#define SLOTS  512   // float4 output slots per row

__device__ __forceinline__ float leaky(float v) {
    return (v >= 0.0f) ? v : 0.01f * v;
}

// Interior upsample mids (weights /256): even m=2k taps x[k-2..k+1],
// odd m=2k+1 taps x[k-1..k+2].
__device__ __forceinline__ float yE4(float a, float b, float c, float d) {
    // {-6, 58, 222, -18}/256
    return fmaf(-0.0234375f, a, fmaf(0.2265625f, b, fmaf(0.8671875f, c, -0.0703125f * d)));
}
__device__ __forceinline__ float yO4(float a, float b, float c, float d) {
    // {-18, 222, 58, -6}/256
    return fmaf(-0.0703125f, a, fmaf(0.8671875f, b, fmaf(0.2265625f, c, -0.0234375f * d)));
}

// Interior symmetric downsample over y[0..7]: {-3,-9,29,111,111,29,-9,-3}/256
__device__ __forceinline__ float dsum(const float* y) {
    return fmaf(0.43359375f,  (y[3] + y[4]),
           fmaf(0.11328125f,  (y[2] + y[5]),
           fmaf(-0.03515625f, (y[1] + y[6]),
                -0.01171875f * (y[0] + y[7]))));
}

__global__ __launch_bounds__(256) void cno_lrelu_kernel(
    const float* __restrict__ x, float* __restrict__ out)
{
    const int g   = blockIdx.x * 256 + threadIdx.x;
    const int row = g >> 9;
    const int t   = g & (SLOTS - 1);
    const float* __restrict__ xr = x + (size_t)row * IN_N;
    float4* __restrict__ ov = reinterpret_cast<float4*>(out) + (size_t)row * SLOTS + t;
    float4 r;

    if (t >= 1 && t <= SLOTS - 2) {
        // ================= interior fast path =================
        const float4* __restrict__ xv = reinterpret_cast<const float4*>(xr) + t;
        float4 A = xv[-1], B = xv[0], C = xv[1];
        float xl[12] = { A.x, A.y, A.z, A.w, B.x, B.y, B.z, B.w, C.x, C.y, C.z, C.w };
        // xl[i] = x[4t - 4 + i]

        // 14 mids y[8t-3 .. 8t+10] with leaky applied.
        float ym[14];
#pragma unroll
        for (int p = 0; p < 14; p++) {
            float v;
            if (p & 1) {   // even mid index: m = 8t-3+p = 2k, k = 4t + (p-3)/2
                int i = (p - 3) / 2 + 2;   // xl index of x[k-2]
                v = yE4(xl[i], xl[i + 1], xl[i + 2], xl[i + 3]);
            } else {       // odd mid index: k = 4t + (p-4)/2
                int i = (p - 4) / 2 + 3;   // xl index of x[k-1]
                v = yO4(xl[i], xl[i + 1], xl[i + 2], xl[i + 3]);
            }
            ym[p] = leaky(v);
        }
        r.x = dsum(ym + 0);
        r.y = dsum(ym + 2);
        r.z = dsum(ym + 4);
        r.w = dsum(ym + 6);
    } else if (t == 0) {
        // ================= left edge: outputs 0..3 =================
        const float4* __restrict__ xv = reinterpret_cast<const float4*>(xr);
        float4 A = xv[0], B = xv[1];
        float x0=A.x, x1=A.y, x2=A.z, x3=A.w, x4=B.x, x5=B.y, x6=B.z;

        float y[11];
        y[0]  = leaky(fmaf(222.0f, x0, -18.0f * x1) * (1.0f / 204.0f));
        y[1]  = leaky(fmaf(222.0f, x0, fmaf(58.0f, x1, -6.0f * x2)) * (1.0f / 274.0f));
        y[2]  = leaky(fmaf(58.0f, x0, fmaf(222.0f, x1, -18.0f * x2)) * (1.0f / 262.0f));
        y[3]  = leaky(yO4(x0, x1, x2, x3));   // m=3,  k=1
        y[4]  = leaky(yE4(x0, x1, x2, x3));   // m=4,  k=2
        y[5]  = leaky(yO4(x1, x2, x3, x4));   // m=5,  k=2
        y[6]  = leaky(yE4(x1, x2, x3, x4));   // m=6,  k=3
        y[7]  = leaky(yO4(x2, x3, x4, x5));   // m=7,  k=3
        y[8]  = leaky(yE4(x2, x3, x4, x5));   // m=8,  k=4
        y[9]  = leaky(yO4(x3, x4, x5, x6));   // m=9,  k=4
        y[10] = leaky(yE4(x3, x4, x5, x6));   // m=10, k=5

        r.x = fmaf(111.0f, (y[0] + y[1]),
              fmaf(29.0f, y[2],
              fmaf(-9.0f, y[3], -3.0f * y[4]))) * (1.0f / 239.0f);
        r.y = fmaf(-9.0f, (y[0] + y[5]),
              fmaf(29.0f, (y[1] + y[4]),
              fmaf(111.0f, (y[2] + y[3]), -3.0f * y[6]))) * (1.0f / 259.0f);
        r.z = dsum(y + 1);   // y[1..8], interior weights
        r.w = dsum(y + 3);   // y[3..10]
    } else {
        // ================= right edge: outputs 2044..2047 =================
        const float4* __restrict__ xv = reinterpret_cast<const float4*>(xr);
        float4 A = xv[SLOTS - 2], B = xv[SLOTS - 1];  // x[2040..2047]
        float x2041=A.y, x2042=A.z, x2043=A.w;
        float x2044=B.x, x2045=B.y, x2046=B.z, x2047=B.w;

        // y[i] = mid 4085+i, leaky applied
        float y[11];
        y[0]  = leaky(yO4(x2041, x2042, x2043, x2044));  // m=4085, k=2042
        y[1]  = leaky(yE4(x2041, x2042, x2043, x2044));  // m=4086, k=2043
        y[2]  = leaky(yO4(x2042, x2043, x2044, x2045));  // m=4087, k=2043
        y[3]  = leaky(yE4(x2042, x2043, x2044, x2045));  // m=4088, k=2044
        y[4]  = leaky(yO4(x2043, x2044, x2045, x2046));  // m=4089, k=2044
        y[5]  = leaky(yE4(x2043, x2044, x2045, x2046));  // m=4090, k=2045
        y[6]  = leaky(yO4(x2044, x2045, x2046, x2047));  // m=4091, k=2045
        y[7]  = leaky(yE4(x2044, x2045, x2046, x2047));  // m=4092, k=2046
        y[8]  = leaky(fmaf(-18.0f, x2045, fmaf(222.0f, x2046, 58.0f * x2047)) * (1.0f / 262.0f)); // m=4093
        y[9]  = leaky(fmaf(-6.0f, x2045, fmaf(58.0f, x2046, 222.0f * x2047)) * (1.0f / 274.0f));  // m=4094
        y[10] = leaky(fmaf(-18.0f, x2046, 222.0f * x2047) * (1.0f / 204.0f));                      // m=4095

        r.x = dsum(y + 0);   // o=2044: y[4085..4092], interior weights
        r.y = dsum(y + 2);   // o=2045: y[4087..4094]
        // o=2046: (-3 y4089 - 9 y4090 + 29 y4091 + 111 y4092 + 111 y4093 + 29 y4094 - 9 y4095)/259
        r.z = fmaf(-9.0f, (y[10] + y[5]),
              fmaf(29.0f, (y[9] + y[6]),
              fmaf(111.0f, (y[8] + y[7]), -3.0f * y[4]))) * (1.0f / 259.0f);
        // o=2047: (-3 y4091 - 9 y4092 + 29 y4093 + 111 y4094 + 111 y4095)/239
        r.w = fmaf(111.0f, (y[10] + y[9]),
              fmaf(29.0f, y[8],
              fmaf(-9.0f, y[7], -3.0f * y[6]))) * (1.0f / 239.0f);
    }
    *ov = r;
}

extern "C" void kernel_launch(void* const* d_in, const int* in_sizes, int n_in,
                              void* d_out, int out_size) {
    const float* x = (const float*)d_in[0];
    float* out = (float*)d_out;
    (void)in_sizes; (void)n_in; (void)out_size;
    cno_lrelu_kernel<<<(N_ROWS * SLOTS) / 256, 256>>>(x, out);
}